// round 2
// baseline (speedup 1.0000x reference)
#include <cuda_runtime.h>
#include <math.h>

#define DD   248
#define HH   512
#define NMAX 10000
#define EMAX 100000
#define NNZMAX 4096

// ---- scratch (no allocs allowed -> __device__ globals) ----
__device__ float g_proj[NMAX * DD];     // features @ Wmsg^T
__device__ float g_S[NMAX * DD];        // segment-summed projected sources
__device__ float g_agg[NMAX * DD];      // bracket output
__device__ float g_hidden[NMAX * HH];   // silu(agg@W1^T+b1)
__device__ float g_h2[NMAX * DD];       // hidden@W2^T+b2
__device__ float g_WmsgT[DD * DD];
__device__ float g_W1T[DD * HH];
__device__ float g_W2T[HH * DD];
__device__ int   g_rowptr[DD + 1];
__device__ int   g_Is[NNZMAX];
__device__ int   g_Js[NNZMAX];
__device__ float g_Cs[NNZMAX];

// ---------------- utility kernels ----------------
__global__ void zero_kernel(float* __restrict__ p, int n) {
    int i = blockIdx.x * blockDim.x + threadIdx.x;
    int stride = gridDim.x * blockDim.x;
    for (; i < n; i += stride) p[i] = 0.f;
}

// out[c*R + r] = in[r*C + c]   (in is R x C row-major)
__global__ void transpose_kernel(const float* __restrict__ in, float* __restrict__ out,
                                 int R, int C) {
    int idx = blockIdx.x * blockDim.x + threadIdx.x;
    int stride = gridDim.x * blockDim.x;
    int total = R * C;
    for (; idx < total; idx += stride) {
        int r = idx / C, c = idx - r * C;
        out[c * R + r] = in[idx];
    }
}

// Deterministic CSR-by-K build (stable order within each bucket).
__global__ void build_csr_kernel(const int* __restrict__ Iv, const int* __restrict__ Jv,
                                 const int* __restrict__ Kv, const float* __restrict__ Cv,
                                 int nnz) {
    __shared__ int cnt[DD];
    __shared__ int off[DD + 1];
    int tid = threadIdx.x;
    for (int k = tid; k < DD; k += blockDim.x) cnt[k] = 0;
    __syncthreads();
    for (int t = tid; t < nnz; t += blockDim.x) atomicAdd(&cnt[Kv[t]], 1);
    __syncthreads();
    if (tid == 0) {
        int s = 0;
        for (int k = 0; k < DD; k++) { off[k] = s; s += cnt[k]; }
        off[DD] = s;
    }
    __syncthreads();
    // stable placement: each thread owns output buckets, scans all triples in order
    for (int k = tid; k < DD; k += blockDim.x) {
        int pos = off[k];
        for (int t = 0; t < nnz; t++) {
            if (Kv[t] == k) {
                g_Is[pos] = Iv[t];
                g_Js[pos] = Jv[t];
                g_Cs[pos] = Cv[t];
                pos++;
            }
        }
    }
    for (int k = tid; k <= DD; k += blockDim.x) g_rowptr[k] = off[k];
}

// S[tgt[e]] += proj[src[e]]  (one block per edge, thread per feature dim)
__global__ void scatter_edges_kernel(const int* __restrict__ ei,
                                     const float* __restrict__ proj,
                                     float* __restrict__ S, int E) {
    int e = blockIdx.x;
    int d = threadIdx.x;
    if (e >= E || d >= DD) return;
    int s = ei[e];
    int t = ei[E + e];
    atomicAdd(&S[t * DD + d], proj[s * DD + d]);
}

// agg[n,k] = sum over CSR row k:  C * S[n,I] * f[n,J]
__global__ void bracket_kernel(const float* __restrict__ S, const float* __restrict__ F,
                               float* __restrict__ agg) {
    __shared__ float sS[DD];
    __shared__ float sF[DD];
    int n = blockIdx.x;
    int tid = threadIdx.x;
    if (tid < DD) {
        sS[tid] = S[n * DD + tid];
        sF[tid] = F[n * DD + tid];
    }
    __syncthreads();
    if (tid < DD) {
        int b = g_rowptr[tid];
        int e = g_rowptr[tid + 1];
        float acc = 0.f;
        for (int t = b; t < e; t++)
            acc += g_Cs[t] * sS[g_Is[t]] * sF[g_Js[t]];
        agg[n * DD + tid] = acc;
    }
}

// ---------------- SGEMM: C = A(MxK) @ B(KxN) [+bias] [silu] ----------------
// 64x64 block tile, 16 K-tile, 4x4 per thread, 256 threads.
template <int ACT>
__global__ __launch_bounds__(256) void sgemm_kernel(const float* __restrict__ A,
                                                    const float* __restrict__ B,
                                                    const float* __restrict__ bias,
                                                    float* __restrict__ C,
                                                    int M, int N, int K) {
    const int BM = 64, BN = 64, BK = 16;
    __shared__ float As[BK][BM];
    __shared__ float Bs[BK][BN];

    int tid = threadIdx.x;
    int m0 = blockIdx.x * BM;
    int n0 = blockIdx.y * BN;
    int tx = tid & 15;        // 0..15 -> 4 cols each
    int ty = tid >> 4;        // 0..15 -> 4 rows each
    int ty4 = ty * 4, tx4 = tx * 4;

    float c[4][4];
#pragma unroll
    for (int i = 0; i < 4; i++)
#pragma unroll
        for (int j = 0; j < 4; j++) c[i][j] = 0.f;

    // load mappings
    int am = tid >> 2;            // 0..63
    int akq = (tid & 3) * 4;      // 0,4,8,12
    int bk = tid >> 4;            // 0..15
    int bnq = (tid & 15) * 4;     // 0..60

    for (int k0 = 0; k0 < K; k0 += BK) {
        int gm = m0 + am;
#pragma unroll
        for (int i = 0; i < 4; i++) {
            int gk = k0 + akq + i;
            As[akq + i][am] = (gm < M && gk < K) ? A[gm * K + gk] : 0.f;
        }
        int gkb = k0 + bk;
#pragma unroll
        for (int j = 0; j < 4; j++) {
            int gn = n0 + bnq + j;
            Bs[bk][bnq + j] = (gkb < K && gn < N) ? B[gkb * N + gn] : 0.f;
        }
        __syncthreads();
#pragma unroll
        for (int k = 0; k < BK; k++) {
            float a[4], b[4];
#pragma unroll
            for (int i = 0; i < 4; i++) a[i] = As[k][ty4 + i];
#pragma unroll
            for (int j = 0; j < 4; j++) b[j] = Bs[k][tx4 + j];
#pragma unroll
            for (int i = 0; i < 4; i++)
#pragma unroll
                for (int j = 0; j < 4; j++) c[i][j] += a[i] * b[j];
        }
        __syncthreads();
    }

#pragma unroll
    for (int i = 0; i < 4; i++) {
        int gm = m0 + ty4 + i;
        if (gm >= M) continue;
#pragma unroll
        for (int j = 0; j < 4; j++) {
            int gn = n0 + tx4 + j;
            if (gn >= N) continue;
            float v = c[i][j];
            if (bias) v += bias[gn];
            if (ACT == 1) v = v / (1.f + expf(-v));  // silu
            C[gm * N + gn] = v;
        }
    }
}

// ---------------- residual + LayerNorm ----------------
__global__ void ln_kernel(const float* __restrict__ F, const float* __restrict__ h2,
                          const float* __restrict__ gamma, const float* __restrict__ beta,
                          float* __restrict__ out) {
    __shared__ float red[256];
    int n = blockIdx.x;
    int tid = threadIdx.x;
    float x = (tid < DD) ? (F[n * DD + tid] + h2[n * DD + tid]) : 0.f;
    red[tid] = x;
    __syncthreads();
#pragma unroll
    for (int s = 128; s > 0; s >>= 1) {
        if (tid < s) red[tid] += red[tid + s];
        __syncthreads();
    }
    float mu = red[0] * (1.f / DD);
    __syncthreads();
    float xc = (tid < DD) ? (x - mu) : 0.f;
    red[tid] = xc * xc;
    __syncthreads();
#pragma unroll
    for (int s = 128; s > 0; s >>= 1) {
        if (tid < s) red[tid] += red[tid + s];
        __syncthreads();
    }
    float var = red[0] * (1.f / DD);
    float r = rsqrtf(var + 1e-5f);
    if (tid < DD)
        out[n * DD + tid] = xc * r * gamma[tid] + beta[tid];
}

// ---------------- launcher ----------------
extern "C" void kernel_launch(void* const* d_in, const int* in_sizes, int n_in,
                              void* d_out, int out_size) {
    const float* features = (const float*)d_in[0];
    const int*   ei       = (const int*)d_in[1];
    const float* Wmsg     = (const float*)d_in[2];
    const float* W1       = (const float*)d_in[3];
    const float* b1       = (const float*)d_in[4];
    const float* W2       = (const float*)d_in[5];
    const float* b2       = (const float*)d_in[6];
    const float* gamma    = (const float*)d_in[7];
    const float* beta     = (const float*)d_in[8];
    const int*   Iv       = (const int*)d_in[9];
    const int*   Jv       = (const int*)d_in[10];
    const int*   Kv       = (const int*)d_in[11];
    const float* Cv       = (const float*)d_in[12];
    float* out = (float*)d_out;

    int N   = in_sizes[0] / DD;
    int E   = in_sizes[1] / 2;
    int nnz = in_sizes[9];

    float *p_proj, *p_S, *p_agg, *p_hidden, *p_h2, *p_WmsgT, *p_W1T, *p_W2T;
    cudaGetSymbolAddress((void**)&p_proj,   g_proj);
    cudaGetSymbolAddress((void**)&p_S,      g_S);
    cudaGetSymbolAddress((void**)&p_agg,    g_agg);
    cudaGetSymbolAddress((void**)&p_hidden, g_hidden);
    cudaGetSymbolAddress((void**)&p_h2,     g_h2);
    cudaGetSymbolAddress((void**)&p_WmsgT,  g_WmsgT);
    cudaGetSymbolAddress((void**)&p_W1T,    g_W1T);
    cudaGetSymbolAddress((void**)&p_W2T,    g_W2T);

    // zero S (atomic accumulator)
    zero_kernel<<<256, 256>>>(p_S, N * DD);

    // weight transposes (B operands in KxN row-major for coalesced tile loads)
    transpose_kernel<<<128, 256>>>(Wmsg, p_WmsgT, DD, DD);
    transpose_kernel<<<128, 256>>>(W1,   p_W1T,   HH, DD);
    transpose_kernel<<<128, 256>>>(W2,   p_W2T,   DD, HH);

    // deterministic CSR of structure constants by output index K
    build_csr_kernel<<<1, 256>>>(Iv, Jv, Kv, Cv, nnz);

    // proj = features @ Wmsg^T
    {
        dim3 grid((N + 63) / 64, (DD + 63) / 64);
        sgemm_kernel<0><<<grid, 256>>>(features, p_WmsgT, nullptr, p_proj, N, DD, DD);
    }

    // S[tgt] += proj[src]
    scatter_edges_kernel<<<E, 256>>>(ei, p_proj, p_S, E);

    // agg[n,k] = sum_t C_t * S[n,I_t] * f[n,J_t]
    bracket_kernel<<<N, 256>>>(p_S, features, p_agg);

    // hidden = silu(agg @ W1^T + b1)
    {
        dim3 grid((N + 63) / 64, (HH + 63) / 64);
        sgemm_kernel<1><<<grid, 256>>>(p_agg, p_W1T, b1, p_hidden, N, HH, DD);
    }

    // h2 = hidden @ W2^T + b2
    {
        dim3 grid((N + 63) / 64, (DD + 63) / 64);
        sgemm_kernel<0><<<grid, 256>>>(p_hidden, p_W2T, b2, p_h2, N, DD, HH);
    }

    // out = LayerNorm(features + h2) * gamma + beta
    ln_kernel<<<N, 256>>>(features, p_h2, gamma, beta, out);
}

// round 4
// speedup vs baseline: 1.2616x; 1.2616x over previous
#include <cuda_runtime.h>
#include <cuda_bf16.h>
#include <math.h>
#include <stdint.h>

#define DD   248
#define HH   512
#define NMAX 10000
#define NNZMAX 4096

// ---------------- scratch (device globals; no allocs allowed) ----------------
__device__ float g_proj[NMAX * DD];
__device__ float g_S[NMAX * DD];
__device__ float g_h2[NMAX * DD];
__device__ __align__(16) __nv_bfloat16 g_fhi[NMAX * DD];
__device__ __align__(16) __nv_bfloat16 g_flo[NMAX * DD];
__device__ __align__(16) __nv_bfloat16 g_agghi[NMAX * DD];
__device__ __align__(16) __nv_bfloat16 g_agglo[NMAX * DD];
__device__ __align__(16) __nv_bfloat16 g_hidhi[NMAX * HH];
__device__ __align__(16) __nv_bfloat16 g_hidlo[NMAX * HH];
__device__ __align__(16) __nv_bfloat16 g_wmhi[DD * DD];
__device__ __align__(16) __nv_bfloat16 g_wmlo[DD * DD];
__device__ __align__(16) __nv_bfloat16 g_w1hi[HH * DD];
__device__ __align__(16) __nv_bfloat16 g_w1lo[HH * DD];
__device__ __align__(16) __nv_bfloat16 g_w2hi[DD * HH];
__device__ __align__(16) __nv_bfloat16 g_w2lo[DD * HH];
__device__ int   g_rowptr[DD + 1];
__device__ int   g_Is[NNZMAX];
__device__ int   g_Js[NNZMAX];
__device__ float g_Cs[NNZMAX];

// ---------------- elementwise / setup kernels ----------------
__global__ void zero_kernel(float* __restrict__ p, int n) {
    int i = blockIdx.x * blockDim.x + threadIdx.x;
    int stride = gridDim.x * blockDim.x;
    for (; i < n; i += stride) p[i] = 0.f;
}

__global__ void split_kernel(const float* __restrict__ x,
                             __nv_bfloat16* __restrict__ hi,
                             __nv_bfloat16* __restrict__ lo, int n) {
    int i = blockIdx.x * blockDim.x + threadIdx.x;
    int stride = gridDim.x * blockDim.x;
    for (; i < n; i += stride) {
        float v = x[i];
        __nv_bfloat16 h = __float2bfloat16(v);
        hi[i] = h;
        lo[i] = __float2bfloat16(v - __bfloat162float(h));
    }
}

__global__ void build_csr_kernel(const int* __restrict__ Iv, const int* __restrict__ Jv,
                                 const int* __restrict__ Kv, const float* __restrict__ Cv,
                                 int nnz) {
    __shared__ int cnt[DD];
    __shared__ int off[DD + 1];
    int tid = threadIdx.x;
    for (int k = tid; k < DD; k += blockDim.x) cnt[k] = 0;
    __syncthreads();
    for (int t = tid; t < nnz; t += blockDim.x) atomicAdd(&cnt[Kv[t]], 1);
    __syncthreads();
    if (tid == 0) {
        int s = 0;
        for (int k = 0; k < DD; k++) { off[k] = s; s += cnt[k]; }
        off[DD] = s;
    }
    __syncthreads();
    for (int k = tid; k < DD; k += blockDim.x) {
        int pos = off[k];
        for (int t = 0; t < nnz; t++) {
            if (Kv[t] == k) {
                g_Is[pos] = Iv[t]; g_Js[pos] = Jv[t]; g_Cs[pos] = Cv[t];
                pos++;
            }
        }
    }
    for (int k = tid; k <= DD; k += blockDim.x) g_rowptr[k] = off[k];
}

__global__ void scatter_edges_kernel(const int* __restrict__ ei,
                                     const float* __restrict__ proj,
                                     float* __restrict__ S, int E) {
    int e = blockIdx.x;
    int d = threadIdx.x;
    if (e >= E || d >= DD) return;
    int s = ei[e];
    int t = ei[E + e];
    atomicAdd(&S[t * DD + d], proj[s * DD + d]);
}

// agg[n,k] = sum_t C_t * S[n,I_t] * f[n,J_t]; emits bf16 split directly
__global__ void bracket_kernel(const float* __restrict__ S, const float* __restrict__ F,
                               __nv_bfloat16* __restrict__ Ahi,
                               __nv_bfloat16* __restrict__ Alo) {
    __shared__ float sS[DD];
    __shared__ float sF[DD];
    int n = blockIdx.x;
    int tid = threadIdx.x;
    if (tid < DD) {
        sS[tid] = S[n * DD + tid];
        sF[tid] = F[n * DD + tid];
    }
    __syncthreads();
    if (tid < DD) {
        int b = g_rowptr[tid];
        int e = g_rowptr[tid + 1];
        float acc = 0.f;
        for (int t = b; t < e; t++)
            acc += g_Cs[t] * sS[g_Is[t]] * sF[g_Js[t]];
        __nv_bfloat16 h = __float2bfloat16(acc);
        Ahi[n * DD + tid] = h;
        Alo[n * DD + tid] = __float2bfloat16(acc - __bfloat162float(h));
    }
}

// ---------------- warp-MMA (mma.sync bf16) split GEMM ----------------
// C[M,N] = A[M,K] @ B[N,K]^T via AhBh + AhBl + AlBh  (fp32 accumulate)
// CTA tile 128x64, 8 warps (4x2), warp tile 32x32, K chunk 32.
#define MMA16816(c, a, b)                                                     \
    asm volatile(                                                             \
        "mma.sync.aligned.m16n8k16.row.col.f32.bf16.bf16.f32 "                \
        "{%0,%1,%2,%3},{%4,%5,%6,%7},{%8,%9},{%0,%1,%2,%3};"                  \
        : "+f"((c)[0]), "+f"((c)[1]), "+f"((c)[2]), "+f"((c)[3])              \
        : "r"((a)[0]), "r"((a)[1]), "r"((a)[2]), "r"((a)[3]),                 \
          "r"((b)[0]), "r"((b)[1]))

template <int ACT, int SPLIT_OUT>
__global__ __launch_bounds__(256) void hmma_gemm(
    const __nv_bfloat16* __restrict__ Ah, const __nv_bfloat16* __restrict__ Al,
    const __nv_bfloat16* __restrict__ Bh, const __nv_bfloat16* __restrict__ Bl,
    const float* __restrict__ bias,
    float* __restrict__ Cf,
    __nv_bfloat16* __restrict__ Chi, __nv_bfloat16* __restrict__ Clo,
    int M, int N, int K)
{
    const int KPAD = 40;
    __shared__ __align__(16) __nv_bfloat16 sA[2][128][KPAD];
    __shared__ __align__(16) __nv_bfloat16 sB[2][64][KPAD];

    int tid = threadIdx.x;
    int wid = tid >> 5;
    int lane = tid & 31;
    int g = lane >> 2;        // 0..7
    int tg = lane & 3;        // 0..3
    int wm = wid >> 1;        // 0..3  (M)
    int wn = wid & 1;         // 0..1  (N)
    int m0 = blockIdx.x * 128;
    int n0 = blockIdx.y * 64;

    float acc[2][4][4];
#pragma unroll
    for (int mi = 0; mi < 2; mi++)
#pragma unroll
        for (int ni = 0; ni < 4; ni++)
#pragma unroll
            for (int q = 0; q < 4; q++) acc[mi][ni][q] = 0.f;

    const uint4 z4 = make_uint4(0u, 0u, 0u, 0u);
    int nkc = (K + 31) >> 5;

    for (int c = 0; c < nkc; ++c) {
        int kc = c << 5;
        // ---- A tiles: 128 rows x 32 cols, hi+lo.  512 uint4 per plane. ----
#pragma unroll
        for (int r = 0; r < 2; ++r) {
            int idx = tid + (r << 8);
            int row = idx >> 2;
            int seg = idx & 3;
            int gm = m0 + row;
            int k = kc + seg * 8;
            uint4 vh = z4, vl = z4;
            if (gm < M && k < K) {
                vh = *(const uint4*)(Ah + (size_t)gm * K + k);
                vl = *(const uint4*)(Al + (size_t)gm * K + k);
            }
            *(uint4*)&sA[0][row][seg * 8] = vh;
            *(uint4*)&sA[1][row][seg * 8] = vl;
        }
        // ---- B tiles: 64 rows x 32 cols ----
        {
            int row = tid >> 2;
            int seg = tid & 3;
            int gn = n0 + row;
            int k = kc + seg * 8;
            uint4 vh = z4, vl = z4;
            if (gn < N && k < K) {
                vh = *(const uint4*)(Bh + (size_t)gn * K + k);
                vl = *(const uint4*)(Bl + (size_t)gn * K + k);
            }
            *(uint4*)&sB[0][row][seg * 8] = vh;
            *(uint4*)&sB[1][row][seg * 8] = vl;
        }
        __syncthreads();

#pragma unroll
        for (int ks = 0; ks < 32; ks += 16) {
            uint32_t ah[2][4], al[2][4], bh[4][2], bl[4][2];
#pragma unroll
            for (int mi = 0; mi < 2; mi++) {
                int mb = wm * 32 + mi * 16;
                ah[mi][0] = *(const uint32_t*)&sA[0][mb + g][ks + tg * 2];
                ah[mi][1] = *(const uint32_t*)&sA[0][mb + g + 8][ks + tg * 2];
                ah[mi][2] = *(const uint32_t*)&sA[0][mb + g][ks + tg * 2 + 8];
                ah[mi][3] = *(const uint32_t*)&sA[0][mb + g + 8][ks + tg * 2 + 8];
                al[mi][0] = *(const uint32_t*)&sA[1][mb + g][ks + tg * 2];
                al[mi][1] = *(const uint32_t*)&sA[1][mb + g + 8][ks + tg * 2];
                al[mi][2] = *(const uint32_t*)&sA[1][mb + g][ks + tg * 2 + 8];
                al[mi][3] = *(const uint32_t*)&sA[1][mb + g + 8][ks + tg * 2 + 8];
            }
#pragma unroll
            for (int ni = 0; ni < 4; ni++) {
                int nb = wn * 32 + ni * 8 + g;
                bh[ni][0] = *(const uint32_t*)&sB[0][nb][ks + tg * 2];
                bh[ni][1] = *(const uint32_t*)&sB[0][nb][ks + tg * 2 + 8];
                bl[ni][0] = *(const uint32_t*)&sB[1][nb][ks + tg * 2];
                bl[ni][1] = *(const uint32_t*)&sB[1][nb][ks + tg * 2 + 8];
            }
#pragma unroll
            for (int mi = 0; mi < 2; mi++)
#pragma unroll
                for (int ni = 0; ni < 4; ni++) {
                    MMA16816(acc[mi][ni], ah[mi], bh[ni]);
                    MMA16816(acc[mi][ni], ah[mi], bl[ni]);
                    MMA16816(acc[mi][ni], al[mi], bh[ni]);
                }
        }
        __syncthreads();
    }

    // ---- epilogue ----
#pragma unroll
    for (int mi = 0; mi < 2; mi++) {
#pragma unroll
        for (int ni = 0; ni < 4; ni++) {
#pragma unroll
            for (int h = 0; h < 2; h++) {     // row halves (g, g+8)
                int gm = m0 + wm * 32 + mi * 16 + g + h * 8;
                if (gm >= M) continue;
#pragma unroll
                for (int q = 0; q < 2; q++) { // col pair
                    int gn = n0 + wn * 32 + ni * 8 + tg * 2 + q;
                    if (gn >= N) continue;
                    float v = acc[mi][ni][h * 2 + q];
                    if (bias) v += bias[gn];
                    if (ACT == 1) v = v / (1.f + expf(-v));
                    if (SPLIT_OUT == 1) {
                        __nv_bfloat16 hh = __float2bfloat16(v);
                        Chi[(size_t)gm * N + gn] = hh;
                        Clo[(size_t)gm * N + gn] =
                            __float2bfloat16(v - __bfloat162float(hh));
                    } else {
                        Cf[(size_t)gm * N + gn] = v;
                    }
                }
            }
        }
    }
}

// ---------------- residual + LayerNorm ----------------
__global__ void ln_kernel(const float* __restrict__ F, const float* __restrict__ h2,
                          const float* __restrict__ gamma, const float* __restrict__ beta,
                          float* __restrict__ out) {
    __shared__ float red[256];
    int n = blockIdx.x;
    int tid = threadIdx.x;
    float x = (tid < DD) ? (F[n * DD + tid] + h2[n * DD + tid]) : 0.f;
    red[tid] = x;
    __syncthreads();
#pragma unroll
    for (int s = 128; s > 0; s >>= 1) {
        if (tid < s) red[tid] += red[tid + s];
        __syncthreads();
    }
    float mu = red[0] * (1.f / DD);
    __syncthreads();
    float xc = (tid < DD) ? (x - mu) : 0.f;
    red[tid] = xc * xc;
    __syncthreads();
#pragma unroll
    for (int s = 128; s > 0; s >>= 1) {
        if (tid < s) red[tid] += red[tid + s];
        __syncthreads();
    }
    float var = red[0] * (1.f / DD);
    float r = rsqrtf(var + 1e-5f);
    if (tid < DD)
        out[n * DD + tid] = xc * r * gamma[tid] + beta[tid];
}

// ---------------- launcher ----------------
extern "C" void kernel_launch(void* const* d_in, const int* in_sizes, int n_in,
                              void* d_out, int out_size) {
    const float* features = (const float*)d_in[0];
    const int*   ei       = (const int*)d_in[1];
    const float* Wmsg     = (const float*)d_in[2];
    const float* W1       = (const float*)d_in[3];
    const float* b1       = (const float*)d_in[4];
    const float* W2       = (const float*)d_in[5];
    const float* b2       = (const float*)d_in[6];
    const float* gamma    = (const float*)d_in[7];
    const float* beta     = (const float*)d_in[8];
    const int*   Iv       = (const int*)d_in[9];
    const int*   Jv       = (const int*)d_in[10];
    const int*   Kv       = (const int*)d_in[11];
    const float* Cv       = (const float*)d_in[12];
    float* out = (float*)d_out;

    int N   = in_sizes[0] / DD;
    int E   = in_sizes[1] / 2;
    int nnz = in_sizes[9];

    float *p_proj, *p_S, *p_h2;
    __nv_bfloat16 *p_fhi, *p_flo, *p_agghi, *p_agglo, *p_hidhi, *p_hidlo;
    __nv_bfloat16 *p_wmhi, *p_wmlo, *p_w1hi, *p_w1lo, *p_w2hi, *p_w2lo;
    cudaGetSymbolAddress((void**)&p_proj,  g_proj);
    cudaGetSymbolAddress((void**)&p_S,     g_S);
    cudaGetSymbolAddress((void**)&p_h2,    g_h2);
    cudaGetSymbolAddress((void**)&p_fhi,   g_fhi);
    cudaGetSymbolAddress((void**)&p_flo,   g_flo);
    cudaGetSymbolAddress((void**)&p_agghi, g_agghi);
    cudaGetSymbolAddress((void**)&p_agglo, g_agglo);
    cudaGetSymbolAddress((void**)&p_hidhi, g_hidhi);
    cudaGetSymbolAddress((void**)&p_hidlo, g_hidlo);
    cudaGetSymbolAddress((void**)&p_wmhi,  g_wmhi);
    cudaGetSymbolAddress((void**)&p_wmlo,  g_wmlo);
    cudaGetSymbolAddress((void**)&p_w1hi,  g_w1hi);
    cudaGetSymbolAddress((void**)&p_w1lo,  g_w1lo);
    cudaGetSymbolAddress((void**)&p_w2hi,  g_w2hi);
    cudaGetSymbolAddress((void**)&p_w2lo,  g_w2lo);

    // zero segment-sum accumulator
    zero_kernel<<<256, 256>>>(p_S, N * DD);

    // bf16 splits of features and weights (B = torch [out,in] = [N,K] directly)
    split_kernel<<<512, 256>>>(features, p_fhi, p_flo, N * DD);
    split_kernel<<<64, 256>>>(Wmsg, p_wmhi, p_wmlo, DD * DD);
    split_kernel<<<128, 256>>>(W1,   p_w1hi, p_w1lo, HH * DD);
    split_kernel<<<128, 256>>>(W2,   p_w2hi, p_w2lo, DD * HH);

    // deterministic CSR of structure constants by output index K
    build_csr_kernel<<<1, 256>>>(Iv, Jv, Kv, Cv, nnz);

    int mtiles = (N + 127) / 128;

    // proj = features @ Wmsg^T   (fp32 out)
    hmma_gemm<0, 0><<<dim3(mtiles, (DD + 63) / 64), 256>>>(
        p_fhi, p_flo, p_wmhi, p_wmlo, nullptr, p_proj, nullptr, nullptr, N, DD, DD);

    // S[tgt] += proj[src]
    scatter_edges_kernel<<<E, 256>>>(ei, p_proj, p_S, E);

    // agg = bracket(S, features), emitted pre-split
    bracket_kernel<<<N, 256>>>(p_S, features, p_agghi, p_agglo);

    // hidden = silu(agg @ W1^T + b1), emitted pre-split
    hmma_gemm<1, 1><<<dim3(mtiles, (HH + 63) / 64), 256>>>(
        p_agghi, p_agglo, p_w1hi, p_w1lo, b1, nullptr, p_hidhi, p_hidlo, N, HH, DD);

    // h2 = hidden @ W2^T + b2   (fp32 out)
    hmma_gemm<0, 0><<<dim3(mtiles, (DD + 63) / 64), 256>>>(
        p_hidhi, p_hidlo, p_w2hi, p_w2lo, b2, p_h2, nullptr, nullptr, N, DD, HH);

    // out = LayerNorm(features + h2)
    ln_kernel<<<N, 256>>>(features, p_h2, gamma, beta, out);
}

// round 5
// speedup vs baseline: 1.5136x; 1.1997x over previous
#include <cuda_runtime.h>
#include <cuda_bf16.h>
#include <math.h>
#include <stdint.h>

#define DD   248
#define HH   512
#define NMAX 10000
#define NNZMAX 4096

// ---------------- scratch (device globals; no allocs allowed) ----------------
__device__ float g_proj[NMAX * DD];
__device__ float g_S[NMAX * DD];
__device__ float g_h2[NMAX * DD];
__device__ __align__(16) __nv_bfloat16 g_fhi[NMAX * DD];
__device__ __align__(16) __nv_bfloat16 g_flo[NMAX * DD];
__device__ __align__(16) __nv_bfloat16 g_agghi[NMAX * DD];
__device__ __align__(16) __nv_bfloat16 g_agglo[NMAX * DD];
__device__ __align__(16) __nv_bfloat16 g_hidhi[NMAX * HH];
__device__ __align__(16) __nv_bfloat16 g_hidlo[NMAX * HH];
__device__ __align__(16) __nv_bfloat16 g_wmhi[DD * DD];
__device__ __align__(16) __nv_bfloat16 g_wmlo[DD * DD];
__device__ __align__(16) __nv_bfloat16 g_w1hi[HH * DD];
__device__ __align__(16) __nv_bfloat16 g_w1lo[HH * DD];
__device__ __align__(16) __nv_bfloat16 g_w2hi[DD * HH];
__device__ __align__(16) __nv_bfloat16 g_w2lo[DD * HH];
__device__ int   g_rowptr[DD + 1];
__device__ int   g_Is[NNZMAX];
__device__ int   g_Js[NNZMAX];
__device__ float g_Cs[NNZMAX];

// ---------------- elementwise / setup kernels ----------------
__global__ void zero_kernel(float* __restrict__ p, int n) {
    int i = blockIdx.x * blockDim.x + threadIdx.x;
    int stride = gridDim.x * blockDim.x;
    for (; i < n; i += stride) p[i] = 0.f;
}

__global__ void split_kernel(const float* __restrict__ x,
                             __nv_bfloat16* __restrict__ hi,
                             __nv_bfloat16* __restrict__ lo, int n) {
    int i = blockIdx.x * blockDim.x + threadIdx.x;
    int stride = gridDim.x * blockDim.x;
    for (; i < n; i += stride) {
        float v = x[i];
        __nv_bfloat16 h = __float2bfloat16(v);
        hi[i] = h;
        lo[i] = __float2bfloat16(v - __bfloat162float(h));
    }
}

__global__ void build_csr_kernel(const int* __restrict__ Iv, const int* __restrict__ Jv,
                                 const int* __restrict__ Kv, const float* __restrict__ Cv,
                                 int nnz) {
    __shared__ int cnt[DD];
    __shared__ int off[DD + 1];
    int tid = threadIdx.x;
    for (int k = tid; k < DD; k += blockDim.x) cnt[k] = 0;
    __syncthreads();
    for (int t = tid; t < nnz; t += blockDim.x) atomicAdd(&cnt[Kv[t]], 1);
    __syncthreads();
    if (tid == 0) {
        int s = 0;
        for (int k = 0; k < DD; k++) { off[k] = s; s += cnt[k]; }
        off[DD] = s;
    }
    __syncthreads();
    for (int k = tid; k < DD; k += blockDim.x) {
        int pos = off[k];
        for (int t = 0; t < nnz; t++) {
            if (Kv[t] == k) {
                g_Is[pos] = Iv[t]; g_Js[pos] = Jv[t]; g_Cs[pos] = Cv[t];
                pos++;
            }
        }
    }
    for (int k = tid; k <= DD; k += blockDim.x) g_rowptr[k] = off[k];
}

// S[tgt[e]] += proj[src[e]] : 64 threads per edge, float4 vectorized atomics
__global__ void scatter_edges_kernel(const int* __restrict__ ei,
                                     const float* __restrict__ proj,
                                     float* __restrict__ S, int E) {
    int gid = blockIdx.x * blockDim.x + threadIdx.x;
    int e = gid >> 6;
    int c = gid & 63;
    if (e >= E || c >= DD / 4) return;
    int s = ei[e];
    int t = ei[E + e];
    float4 v = *(const float4*)(proj + (size_t)s * DD + c * 4);
#if __CUDA_ARCH__ >= 900
    atomicAdd((float4*)(S + (size_t)t * DD + c * 4), v);
#else
    float* p = S + (size_t)t * DD + c * 4;
    atomicAdd(p + 0, v.x); atomicAdd(p + 1, v.y);
    atomicAdd(p + 2, v.z); atomicAdd(p + 3, v.w);
#endif
}

// agg[n,k] = sum_t C_t * S[n,I_t] * f[n,J_t]; emits bf16 split directly
__global__ void bracket_kernel(const float* __restrict__ S, const float* __restrict__ F,
                               __nv_bfloat16* __restrict__ Ahi,
                               __nv_bfloat16* __restrict__ Alo) {
    __shared__ float sS[DD];
    __shared__ float sF[DD];
    int n = blockIdx.x;
    int tid = threadIdx.x;
    if (tid < DD) {
        sS[tid] = S[n * DD + tid];
        sF[tid] = F[n * DD + tid];
    }
    __syncthreads();
    if (tid < DD) {
        int b = g_rowptr[tid];
        int e = g_rowptr[tid + 1];
        float acc = 0.f;
        for (int t = b; t < e; t++)
            acc += g_Cs[t] * sS[g_Is[t]] * sF[g_Js[t]];
        __nv_bfloat16 h = __float2bfloat16(acc);
        Ahi[n * DD + tid] = h;
        Alo[n * DD + tid] = __float2bfloat16(acc - __bfloat162float(h));
    }
}

// ---------------- warp-MMA (mma.sync bf16) split GEMM v2 ----------------
// C[M,N] = A[M,K] @ B[N,K]^T via AhBh + AhBl + AlBh  (fp32 accumulate)
// CTA 128x64, 8 warps 4x2, warp tile 32x32, BK=32, cp.async double buffer,
// ldmatrix fragment loads. Smem rows padded to 40 elems (80B, conflict-free).
#define MMA16816(c, a, b)                                                     \
    asm volatile(                                                             \
        "mma.sync.aligned.m16n8k16.row.col.f32.bf16.bf16.f32 "                \
        "{%0,%1,%2,%3},{%4,%5,%6,%7},{%8,%9},{%0,%1,%2,%3};"                  \
        : "+f"((c)[0]), "+f"((c)[1]), "+f"((c)[2]), "+f"((c)[3])              \
        : "r"((a)[0]), "r"((a)[1]), "r"((a)[2]), "r"((a)[3]),                 \
          "r"((b)[0]), "r"((b)[1]))

#define LDSM4(r0, r1, r2, r3, addr)                                           \
    asm volatile("ldmatrix.sync.aligned.m8n8.x4.shared.b16 {%0,%1,%2,%3}, [%4];" \
                 : "=r"(r0), "=r"(r1), "=r"(r2), "=r"(r3) : "r"(addr))

#define CPASYNC16(saddr, gaddr, sz)                                           \
    asm volatile("cp.async.cg.shared.global [%0], [%1], 16, %2;"              \
                 :: "r"(saddr), "l"(gaddr), "r"(sz) : "memory")

// per-buffer layout (bytes): Ah 128*80 | Al 128*80 | Bh 64*80 | Bl 64*80
#define BUF_BYTES   30720u
#define A_PLANE     10240u
#define B_OFF       20480u
#define B_PLANE     5120u
#define ROWB        80u

__device__ __forceinline__ uint32_t smem_u32(const void* p) {
    uint32_t a;
    asm("{ .reg .u64 t; cvta.to.shared.u64 t, %1; cvt.u32.u64 %0, t; }"
        : "=r"(a) : "l"(p));
    return a;
}

template <int ACT, int SPLIT_OUT>
__global__ __launch_bounds__(256) void hmma_gemm(
    const __nv_bfloat16* __restrict__ Ah, const __nv_bfloat16* __restrict__ Al,
    const __nv_bfloat16* __restrict__ Bh, const __nv_bfloat16* __restrict__ Bl,
    const float* __restrict__ bias,
    float* __restrict__ Cf,
    __nv_bfloat16* __restrict__ Chi, __nv_bfloat16* __restrict__ Clo,
    int M, int N, int K)
{
    extern __shared__ char smem[];
    uint32_t sbase = smem_u32(smem);

    int tid = threadIdx.x;
    int wid = tid >> 5;
    int lane = tid & 31;
    int g = lane >> 2;
    int tg = lane & 3;
    int wm = wid >> 1;
    int wn = wid & 1;
    int m0 = blockIdx.x * 128;
    int n0 = blockIdx.y * 64;

    // ldmatrix per-lane row/col components
    int lr = lane & 7;
    int lm01 = (lane >> 3) & 1;  // lm&1
    int lm23 = lane >> 4;        // lm>>1

    float acc[2][4][4];
#pragma unroll
    for (int mi = 0; mi < 2; mi++)
#pragma unroll
        for (int ni = 0; ni < 4; ni++)
#pragma unroll
            for (int q = 0; q < 4; q++) acc[mi][ni][q] = 0.f;

    int nkc = (K + 31) >> 5;

    // ---- async tile loader for chunk c into buffer (c&1) ----
    auto issue_chunk = [&](int c) {
        int kc = c << 5;
        uint32_t bufb = sbase + (uint32_t)(c & 1) * BUF_BYTES;
        // A: 1024 16B chunks (2 planes x 128 rows x 4 segs), 4 per thread
#pragma unroll
        for (int r = 0; r < 4; ++r) {
            int i = tid + (r << 8);
            int plane = i >> 9;
            int row = (i >> 2) & 127;
            int seg = i & 3;
            int gm = m0 + row;
            int k = kc + seg * 8;
            const __nv_bfloat16* src = (plane ? Al : Ah) + (size_t)gm * K + k;
            uint32_t dst = bufb + (uint32_t)plane * A_PLANE + (uint32_t)row * ROWB
                           + (uint32_t)seg * 16u;
            uint32_t sz = (gm < M && k < K) ? 16u : 0u;
            CPASYNC16(dst, src, sz);
        }
        // B: 512 16B chunks (2 planes x 64 rows x 4 segs), 2 per thread
#pragma unroll
        for (int r = 0; r < 2; ++r) {
            int i = tid + (r << 8);
            int plane = i >> 8;
            int row = (i >> 2) & 63;
            int seg = i & 3;
            int gn = n0 + row;
            int k = kc + seg * 8;
            const __nv_bfloat16* src = (plane ? Bl : Bh) + (size_t)gn * K + k;
            uint32_t dst = bufb + B_OFF + (uint32_t)plane * B_PLANE
                           + (uint32_t)row * ROWB + (uint32_t)seg * 16u;
            uint32_t sz = (gn < N && k < K) ? 16u : 0u;
            CPASYNC16(dst, src, sz);
        }
        asm volatile("cp.async.commit_group;" ::: "memory");
    };

    issue_chunk(0);

    for (int c = 0; c < nkc; ++c) {
        if (c + 1 < nkc) {
            issue_chunk(c + 1);
            asm volatile("cp.async.wait_group 1;" ::: "memory");
        } else {
            asm volatile("cp.async.wait_group 0;" ::: "memory");
        }
        __syncthreads();

        uint32_t abase = sbase + (uint32_t)(c & 1) * BUF_BYTES;
        uint32_t bbase = abase + B_OFF;
#pragma unroll
        for (int ks = 0; ks < 32; ks += 16) {
            uint32_t ah[2][4], al[2][4], bh[4][2], bl[4][2];
#pragma unroll
            for (int mi = 0; mi < 2; mi++) {
                uint32_t row = (uint32_t)(wm * 32 + mi * 16 + lm01 * 8 + lr);
                uint32_t col = (uint32_t)(ks + lm23 * 8);
                uint32_t off = row * ROWB + col * 2u;
                LDSM4(ah[mi][0], ah[mi][1], ah[mi][2], ah[mi][3], abase + off);
                LDSM4(al[mi][0], al[mi][1], al[mi][2], al[mi][3],
                      abase + A_PLANE + off);
            }
#pragma unroll
            for (int ng = 0; ng < 2; ng++) {
                uint32_t row = (uint32_t)(wn * 32 + ng * 16 + lm23 * 8 + lr);
                uint32_t col = (uint32_t)(ks + lm01 * 8);
                uint32_t off = row * ROWB + col * 2u;
                LDSM4(bh[2 * ng][0], bh[2 * ng][1], bh[2 * ng + 1][0],
                      bh[2 * ng + 1][1], bbase + off);
                LDSM4(bl[2 * ng][0], bl[2 * ng][1], bl[2 * ng + 1][0],
                      bl[2 * ng + 1][1], bbase + B_PLANE + off);
            }
#pragma unroll
            for (int mi = 0; mi < 2; mi++)
#pragma unroll
                for (int ni = 0; ni < 4; ni++) {
                    MMA16816(acc[mi][ni], ah[mi], bh[ni]);
                    MMA16816(acc[mi][ni], ah[mi], bl[ni]);
                    MMA16816(acc[mi][ni], al[mi], bh[ni]);
                }
        }
        __syncthreads();
    }

    // ---- epilogue ----
#pragma unroll
    for (int mi = 0; mi < 2; mi++) {
#pragma unroll
        for (int ni = 0; ni < 4; ni++) {
#pragma unroll
            for (int h = 0; h < 2; h++) {
                int gm = m0 + wm * 32 + mi * 16 + g + h * 8;
                if (gm >= M) continue;
#pragma unroll
                for (int q = 0; q < 2; q++) {
                    int gn = n0 + wn * 32 + ni * 8 + tg * 2 + q;
                    if (gn >= N) continue;
                    float v = acc[mi][ni][h * 2 + q];
                    if (bias) v += bias[gn];
                    if (ACT == 1) v = v / (1.f + expf(-v));
                    if (SPLIT_OUT == 1) {
                        __nv_bfloat16 hh = __float2bfloat16(v);
                        Chi[(size_t)gm * N + gn] = hh;
                        Clo[(size_t)gm * N + gn] =
                            __float2bfloat16(v - __bfloat162float(hh));
                    } else {
                        Cf[(size_t)gm * N + gn] = v;
                    }
                }
            }
        }
    }
}

// ---------------- residual + LayerNorm ----------------
__global__ void ln_kernel(const float* __restrict__ F, const float* __restrict__ h2,
                          const float* __restrict__ gamma, const float* __restrict__ beta,
                          float* __restrict__ out) {
    __shared__ float red[256];
    int n = blockIdx.x;
    int tid = threadIdx.x;
    float x = (tid < DD) ? (F[n * DD + tid] + h2[n * DD + tid]) : 0.f;
    red[tid] = x;
    __syncthreads();
#pragma unroll
    for (int s = 128; s > 0; s >>= 1) {
        if (tid < s) red[tid] += red[tid + s];
        __syncthreads();
    }
    float mu = red[0] * (1.f / DD);
    __syncthreads();
    float xc = (tid < DD) ? (x - mu) : 0.f;
    red[tid] = xc * xc;
    __syncthreads();
#pragma unroll
    for (int s = 128; s > 0; s >>= 1) {
        if (tid < s) red[tid] += red[tid + s];
        __syncthreads();
    }
    float var = red[0] * (1.f / DD);
    float r = rsqrtf(var + 1e-5f);
    if (tid < DD)
        out[n * DD + tid] = xc * r * gamma[tid] + beta[tid];
}

// ---------------- launcher ----------------
extern "C" void kernel_launch(void* const* d_in, const int* in_sizes, int n_in,
                              void* d_out, int out_size) {
    const float* features = (const float*)d_in[0];
    const int*   ei       = (const int*)d_in[1];
    const float* Wmsg     = (const float*)d_in[2];
    const float* W1       = (const float*)d_in[3];
    const float* b1       = (const float*)d_in[4];
    const float* W2       = (const float*)d_in[5];
    const float* b2       = (const float*)d_in[6];
    const float* gamma    = (const float*)d_in[7];
    const float* beta     = (const float*)d_in[8];
    const int*   Iv       = (const int*)d_in[9];
    const int*   Jv       = (const int*)d_in[10];
    const int*   Kv       = (const int*)d_in[11];
    const float* Cv       = (const float*)d_in[12];
    float* out = (float*)d_out;

    int N   = in_sizes[0] / DD;
    int E   = in_sizes[1] / 2;
    int nnz = in_sizes[9];

    float *p_proj, *p_S, *p_h2;
    __nv_bfloat16 *p_fhi, *p_flo, *p_agghi, *p_agglo, *p_hidhi, *p_hidlo;
    __nv_bfloat16 *p_wmhi, *p_wmlo, *p_w1hi, *p_w1lo, *p_w2hi, *p_w2lo;
    cudaGetSymbolAddress((void**)&p_proj,  g_proj);
    cudaGetSymbolAddress((void**)&p_S,     g_S);
    cudaGetSymbolAddress((void**)&p_h2,    g_h2);
    cudaGetSymbolAddress((void**)&p_fhi,   g_fhi);
    cudaGetSymbolAddress((void**)&p_flo,   g_flo);
    cudaGetSymbolAddress((void**)&p_agghi, g_agghi);
    cudaGetSymbolAddress((void**)&p_agglo, g_agglo);
    cudaGetSymbolAddress((void**)&p_hidhi, g_hidhi);
    cudaGetSymbolAddress((void**)&p_hidlo, g_hidlo);
    cudaGetSymbolAddress((void**)&p_wmhi,  g_wmhi);
    cudaGetSymbolAddress((void**)&p_wmlo,  g_wmlo);
    cudaGetSymbolAddress((void**)&p_w1hi,  g_w1hi);
    cudaGetSymbolAddress((void**)&p_w1lo,  g_w1lo);
    cudaGetSymbolAddress((void**)&p_w2hi,  g_w2hi);
    cudaGetSymbolAddress((void**)&p_w2lo,  g_w2lo);

    const int SMEM_SZ = 2 * 30720;
    cudaFuncSetAttribute(hmma_gemm<0, 0>, cudaFuncAttributeMaxDynamicSharedMemorySize, SMEM_SZ);
    cudaFuncSetAttribute(hmma_gemm<1, 1>, cudaFuncAttributeMaxDynamicSharedMemorySize, SMEM_SZ);

    // zero segment-sum accumulator
    zero_kernel<<<256, 256>>>(p_S, N * DD);

    // bf16 splits of features and weights (B = torch [out,in] = [N,K] directly)
    split_kernel<<<512, 256>>>(features, p_fhi, p_flo, N * DD);
    split_kernel<<<64, 256>>>(Wmsg, p_wmhi, p_wmlo, DD * DD);
    split_kernel<<<128, 256>>>(W1,   p_w1hi, p_w1lo, HH * DD);
    split_kernel<<<128, 256>>>(W2,   p_w2hi, p_w2lo, DD * HH);

    // deterministic CSR of structure constants by output index K
    build_csr_kernel<<<1, 256>>>(Iv, Jv, Kv, Cv, nnz);

    int mtiles = (N + 127) / 128;

    // proj = features @ Wmsg^T   (fp32 out)
    hmma_gemm<0, 0><<<dim3(mtiles, (DD + 63) / 64), 256, SMEM_SZ>>>(
        p_fhi, p_flo, p_wmhi, p_wmlo, nullptr, p_proj, nullptr, nullptr, N, DD, DD);

    // S[tgt] += proj[src]  (vectorized atomics, 64 thr/edge)
    scatter_edges_kernel<<<(E * 64 + 255) / 256, 256>>>(ei, p_proj, p_S, E);

    // agg = bracket(S, features), emitted pre-split
    bracket_kernel<<<N, 256>>>(p_S, features, p_agghi, p_agglo);

    // hidden = silu(agg @ W1^T + b1), emitted pre-split
    hmma_gemm<1, 1><<<dim3(mtiles, (HH + 63) / 64), 256, SMEM_SZ>>>(
        p_agghi, p_agglo, p_w1hi, p_w1lo, b1, nullptr, p_hidhi, p_hidlo, N, HH, DD);

    // h2 = hidden @ W2^T + b2   (fp32 out)
    hmma_gemm<0, 0><<<dim3(mtiles, (DD + 63) / 64), 256, SMEM_SZ>>>(
        p_hidhi, p_hidlo, p_w2hi, p_w2lo, b2, p_h2, nullptr, nullptr, N, DD, HH);

    // out = LayerNorm(features + h2)
    ln_kernel<<<N, 256>>>(features, p_h2, gamma, beta, out);
}